// round 11
// baseline (speedup 1.0000x reference)
#include <cuda_runtime.h>

// ---------------- scratch (device globals; allocation-free) ----------------
__device__ float g_hA[16384*256];
__device__ float g_hB[16384*256];
__device__ float g_c [16384*256];
__device__ float g_childA[16384*256];
__device__ float g_childB[4096*256];
__device__ float g_xw[16384*1024];
__device__ float g_WcatT[512*1024];     // [k][jj*4+g] (k<256: W_ih, else W_hh)
__device__ float g_Wcomb[256*512];
__device__ float g_WcombHT[256*256];
__device__ float g_bcomb[256];
__device__ float g_tagE[26*256];
__device__ float g_leafout[26*256];
__device__ float g_leafxW[26*1024];
__device__ float g_h1[256];
__device__ float g_c1[256];
__device__ float g_bzT[1024];
__device__ float g_hh1[1024];
__device__ float g_h676[676*256];
__device__ float g_c676[676*256];

// grid barrier state
__device__ int g_barcnt = 0;
__device__ volatile int g_bargen = 0;

__device__ __forceinline__ float sigm(float x){ return 1.0f/(1.0f+expf(-x)); }

#define NB 132

__device__ __forceinline__ void gridbar(){
    __syncthreads();
    if (threadIdx.x == 0){
        int g = g_bargen;
        __threadfence();
        if (atomicAdd(&g_barcnt, 1) == NB-1){
            g_barcnt = 0;
            __threadfence();
            g_bargen = g + 1;
        } else {
            while (g_bargen == g) { }
        }
    }
    __syncthreads();
    __threadfence();
}

// ---------------- prologue A: P1 (wcomb/bcomb/wcatT/bzT/h1c1) | P2 (wcombHT/tagE/hh1) ----
__global__ void __launch_bounds__(256)
k_preA(const float* __restrict__ Wt, const float* __restrict__ Wc,
       const float* __restrict__ bc, const float* __restrict__ bt,
       const float* __restrict__ W_ih, const float* __restrict__ W_hh,
       const float* __restrict__ b_ih, const float* __restrict__ b_hh,
       const float* __restrict__ emb, const float* __restrict__ lstm_init)
{
    __shared__ float sm[1280];
    int tid = threadIdx.x;

    for (int t = blockIdx.x; t < 2563; t += NB){
        if (t < 512){
            int idx = t*256 + tid;
            int i = idx >> 9, k = idx & 511;
            float s = 0.f;
            #pragma unroll 8
            for (int j = 0; j < 256; j++) s += Wt[i*256+j]*Wc[j*512+k];
            g_Wcomb[idx] = s;
        } else if (t == 512){
            float s = bt[tid];
            #pragma unroll 8
            for (int j = 0; j < 256; j++) s += Wt[tid*256+j]*bc[j];
            g_bcomb[tid] = s;
        } else if (t < 2561){
            int idx = (t-513)*256 + tid;
            int k = idx >> 10, col = idx & 1023;
            int jj = col >> 2, g = col & 3;
            int row = g*256 + jj;
            g_WcatT[idx] = (k < 256) ? W_ih[row*256 + k] : W_hh[row*256 + (k-256)];
        } else if (t == 2561){
            #pragma unroll
            for (int rr = 0; rr < 4; rr++){
                int idx = tid + rr*256;
                int jj = idx >> 2, g = idx & 3;
                g_bzT[idx] = b_ih[g*256+jj] + b_hh[g*256+jj];
            }
        } else {
            sm[tid] = lstm_init[tid];
            __syncthreads();
            #pragma unroll
            for (int rr = 0; rr < 4; rr++){
                int j = tid + rr*256;
                float s = b_ih[j] + b_hh[j];
                const float* w = &W_ih[j*256];
                #pragma unroll 8
                for (int k = 0; k < 256; k++) s += sm[k]*w[k];
                sm[256 + j] = s;
            }
            __syncthreads();
            float c = sigm(sm[256+tid]) * tanhf(sm[256+tid+512]);
            g_c1[tid] = c;
            g_h1[tid] = sigm(sm[256+tid+768]) * tanhf(c);
            __syncthreads();
        }
    }
    gridbar();
    for (int t = blockIdx.x; t < 286; t += NB){
        if (t < 256){
            int idx = t*256 + tid;
            int k = idx >> 8, i = idx & 255;
            g_WcombHT[idx] = g_Wcomb[i*512 + k];
        } else if (t < 282){
            int v = t - 256;
            sm[tid] = emb[v*256 + tid];
            __syncthreads();
            float s = 0.f;
            #pragma unroll 8
            for (int k = 0; k < 256; k++) s += sm[k]*g_Wcomb[tid*512 + 256 + k];
            g_tagE[v*256 + tid] = s;
            __syncthreads();
        } else {
            int col = (t-282)*256 + tid;
            sm[tid] = g_h1[tid];
            __syncthreads();
            const float* w = g_WcatT + 256*1024;
            float s = 0.f;
            #pragma unroll 8
            for (int k = 0; k < 256; k++) s += sm[k]*w[k*1024 + col];
            g_hh1[col] = s;
            __syncthreads();
        }
    }
}

// ---------------- prologue B: leafout | leafxw | 676 states ----------------
__global__ void __launch_bounds__(256)
k_preB(const float* __restrict__ W_ih, const float* __restrict__ b_ih,
       const float* __restrict__ b_hh)
{
    __shared__ float sh[16*264];
    __shared__ int rmapS[16], aidxS[16];
    int tid = threadIdx.x;

    for (int t = blockIdx.x; t < 26; t += NB){
        int v = t, i = tid;
        float* h1s = sh;
        float* red = sh + 256;
        h1s[i] = g_h1[i];
        __syncthreads();
        float s = g_tagE[v*256+i] + g_bcomb[i];
        #pragma unroll 8
        for (int k = 0; k < 256; k++) s += h1s[k]*g_Wcomb[i*512 + k];
        red[i] = s; __syncthreads();
        for (int st = 128; st > 0; st >>= 1){ if (i < st) red[i] = fmaxf(red[i], red[i+st]); __syncthreads(); }
        float mx = red[0]; __syncthreads();
        red[i] = expf(s - mx); __syncthreads();
        for (int st = 128; st > 0; st >>= 1){ if (i < st) red[i] += red[i+st]; __syncthreads(); }
        float lse = mx + logf(red[0]);
        g_leafout[v*256 + i] = s - lse;
        __syncthreads();
    }
    gridbar();
    for (int t = blockIdx.x; t < 104; t += NB){
        int v = t >> 2, jb = t & 3;
        int c = jb*256 + tid;
        int jj = c >> 2, g = c & 3;
        int row = g*256 + jj;
        sh[tid] = g_leafout[v*256 + tid];
        __syncthreads();
        float s = b_ih[row] + b_hh[row];
        #pragma unroll 8
        for (int k = 0; k < 256; k++) s += sh[k]*W_ih[row*256 + k];
        g_leafxW[v*1024 + c] = s;
        __syncthreads();
    }
    gridbar();
    const float* whh = g_WcatT + 256*1024;
    for (int t = blockIdx.x; t < 344; t += NB){
        int mblk = t >> 3, j0q = (t & 7)*32, m0 = mblk*16;
        const int M = 676;
        int r = tid >> 4, tj = tid & 15;
        if (tid < 16){
            int gm = m0 + tid;
            int rr = 0, a = 0;
            if (gm < M){ rr = gm/26; a = gm - rr*26; }
            rmapS[tid] = rr; aidxS[tid] = a;
        }
        __syncthreads();
        #pragma unroll
        for (int q = 0; q < 16; q++){
            int e = tid + q*256;
            int row = e >> 8, k = e & 255;
            int i0 = rmapS[row];
            float4 zh = *reinterpret_cast<const float4*>(&g_hh1[k*4]);
            float4 zl = *reinterpret_cast<const float4*>(&g_leafxW[i0*1024 + k*4]);
            float cz = sigm(zh.y+zl.y)*g_c1[k] + sigm(zh.x+zl.x)*tanhf(zh.z+zl.z);
            sh[row*264 + k] = sigm(zh.w+zl.w)*tanhf(cz);
        }
        __syncthreads();
        int q0 = j0q + tj, q1 = q0 + 16;
        float4 acc0 = make_float4(0.f,0.f,0.f,0.f);
        float4 acc1 = make_float4(0.f,0.f,0.f,0.f);
        const float* w0 = whh + q0*4;
        const float* w1 = whh + q1*4;
        #pragma unroll 4
        for (int k = 0; k < 256; k++){
            float a = sh[r*264 + k];
            float4 b0 = *reinterpret_cast<const float4*>(&w0[k*1024]);
            float4 b1 = *reinterpret_cast<const float4*>(&w1[k*1024]);
            acc0.x = fmaf(a,b0.x,acc0.x); acc0.y = fmaf(a,b0.y,acc0.y);
            acc0.z = fmaf(a,b0.z,acc0.z); acc0.w = fmaf(a,b0.w,acc0.w);
            acc1.x = fmaf(a,b1.x,acc1.x); acc1.y = fmaf(a,b1.y,acc1.y);
            acc1.z = fmaf(a,b1.z,acc1.z); acc1.w = fmaf(a,b1.w,acc1.w);
        }
        int gm = m0 + r;
        if (gm < M){
            const float* ad = g_leafxW + aidxS[r]*1024;
            float4 a0 = *reinterpret_cast<const float4*>(&ad[q0*4]);
            float4 a1 = *reinterpret_cast<const float4*>(&ad[q1*4]);
            float4 zh0 = *reinterpret_cast<const float4*>(&g_hh1[q0*4]);
            float4 zl0 = *reinterpret_cast<const float4*>(&g_leafxW[rmapS[r]*1024 + q0*4]);
            float cold0 = sigm(zh0.y+zl0.y)*g_c1[q0] + sigm(zh0.x+zl0.x)*tanhf(zh0.z+zl0.z);
            float4 zh1 = *reinterpret_cast<const float4*>(&g_hh1[q1*4]);
            float4 zl1 = *reinterpret_cast<const float4*>(&g_leafxW[rmapS[r]*1024 + q1*4]);
            float cold1 = sigm(zh1.y+zl1.y)*g_c1[q1] + sigm(zh1.x+zl1.x)*tanhf(zh1.z+zl1.z);
            {
                float zi = acc0.x+a0.x, zf = acc0.y+a0.y, zg = acc0.z+a0.z, zo = acc0.w+a0.w;
                float cn = sigm(zf)*cold0 + sigm(zi)*tanhf(zg);
                g_c676[gm*256 + q0] = cn;
                g_h676[gm*256 + q0] = sigm(zo)*tanhf(cn);
            }
            {
                float zi = acc1.x+a1.x, zf = acc1.y+a1.y, zg = acc1.z+a1.z, zo = acc1.w+a1.w;
                float cn = sigm(zf)*cold1 + sigm(zi)*tanhf(zg);
                g_c676[gm*256 + q1] = cn;
                g_h676[gm*256 + q1] = sigm(zo)*tanhf(cn);
            }
        }
        __syncthreads();
    }
}

// ---------------- SIMT GEMM v3: 128x128 block tile, 16x4 thread tile, K=256 ----------------
// Block: 128 rows x 32 quad-cols (=128 cols), 256 threads, acc[16][4].
// Warp layout: tj = lane (quad), tm = warp (row group of 16) -> As reads broadcast.
// MODE 0: xw: A=child rows, out xw[gm*1024+col] = acc + bzT[col]
// MODE 1: h-step: A=hin[gm], add=xw[(gm*4+t)], cell w/ cin->cout
// MODE 2: L7 t=3: A=hin[gm], add=leafxW[ids[gm*4]], cell
// MODE 4: L7 t=2: A=h676[id0*26+id1], add=leafxW[id2], cold=c676[rmap]
template<int MODE>
__global__ void __launch_bounds__(256)
simt_gemm(const float* __restrict__ hin, float* __restrict__ hout,
          const float* __restrict__ cin, float* __restrict__ cout,
          const float* __restrict__ WT,
          const int* __restrict__ ids,
          const float* __restrict__ addbase,
          int t, int M)
{
    __shared__ float As[16][132];
    __shared__ float Ws[16][128];
    __shared__ int rmap[128], aidx[128];
    int tid = threadIdx.x;
    int tj = tid & 31;          // quad within 32
    int tm = tid >> 5;          // warp id = row group (16 rows)
    int m0 = blockIdx.x * 128;
    int j0 = blockIdx.y * 32;   // quad base

    if (MODE == 2 || MODE == 4){
        if (tid < 128){
            int gm = m0 + tid;
            int r = 0, a = 0;
            if (gm < M){
                if (MODE == 2){ r = gm; a = ids[gm*4]; }
                else { int i0 = ids[gm*4], i1 = ids[gm*4+1]; a = ids[gm*4+2]; r = i0*26 + i1; }
            }
            rmap[tid] = r; aidx[tid] = a;
        }
        __syncthreads();
    }

    float acc[16][4];
    #pragma unroll
    for (int a = 0; a < 16; a++)
        #pragma unroll
        for (int b = 0; b < 4; b++) acc[a][b] = 0.f;

    for (int k0 = 0; k0 < 256; k0 += 16){
        // A: 16 k x 128 m = 2048 floats, 8 per thread
        #pragma unroll
        for (int q = 0; q < 8; q++){
            int e = tid + q*256;
            int m = e >> 4, kk = e & 15;
            int gm = m0 + m;
            float v = 0.f;
            if (gm < M){
                int k = k0 + kk;
                if (MODE == 4) v = hin[rmap[m]*256 + k];
                else           v = hin[gm*256 + k];
            }
            As[kk][m] = v;
        }
        // B: 16 k x 128 cols = 2048 floats, float4 x2 per thread
        #pragma unroll
        for (int q = 0; q < 2; q++){
            int e = tid + q*256;
            int kk = e >> 5, c4 = e & 31;
            *reinterpret_cast<float4*>(&Ws[kk][c4*4]) =
                *reinterpret_cast<const float4*>(&WT[(k0+kk)*1024 + j0*4 + c4*4]);
        }
        __syncthreads();
        #pragma unroll
        for (int kk = 0; kk < 16; kk++){
            float4 b  = *reinterpret_cast<const float4*>(&Ws[kk][tj*4]);
            float4 a0 = *reinterpret_cast<const float4*>(&As[kk][tm*16]);
            float4 a1 = *reinterpret_cast<const float4*>(&As[kk][tm*16+4]);
            float4 a2 = *reinterpret_cast<const float4*>(&As[kk][tm*16+8]);
            float4 a3 = *reinterpret_cast<const float4*>(&As[kk][tm*16+12]);
            float ar[16] = {a0.x,a0.y,a0.z,a0.w, a1.x,a1.y,a1.z,a1.w,
                            a2.x,a2.y,a2.z,a2.w, a3.x,a3.y,a3.z,a3.w};
            #pragma unroll
            for (int mi = 0; mi < 16; mi++){
                acc[mi][0] = fmaf(ar[mi], b.x, acc[mi][0]);
                acc[mi][1] = fmaf(ar[mi], b.y, acc[mi][1]);
                acc[mi][2] = fmaf(ar[mi], b.z, acc[mi][2]);
                acc[mi][3] = fmaf(ar[mi], b.w, acc[mi][3]);
            }
        }
        __syncthreads();
    }

    int jj = j0 + tj;
    #pragma unroll
    for (int mi = 0; mi < 16; mi++){
        int m = tm*16 + mi;
        int gm = m0 + m;
        if (gm >= M) continue;
        float zi = acc[mi][0], zf = acc[mi][1], zg = acc[mi][2], zo = acc[mi][3];
        if (MODE == 0){
            float4 bz = *reinterpret_cast<const float4*>(&addbase[jj*4]);
            float4 v = make_float4(zi+bz.x, zf+bz.y, zg+bz.z, zo+bz.w);
            *reinterpret_cast<float4*>(&hout[gm*1024 + jj*4]) = v;
        } else {
            const float* ad;
            float cold;
            if (MODE == 1){
                ad = addbase + (gm*4 + t)*1024;
                cold = cin[gm*256 + jj];
            } else if (MODE == 2){
                ad = addbase + aidx[m]*1024;
                cold = cin[gm*256 + jj];
            } else {
                ad = addbase + aidx[m]*1024;
                cold = cin[rmap[m]*256 + jj];
            }
            float4 a4 = *reinterpret_cast<const float4*>(&ad[jj*4]);
            zi += a4.x; zf += a4.y; zg += a4.z; zo += a4.w;
            float cn = sigm(zf)*cold + sigm(zi)*tanhf(zg);
            cout[gm*256 + jj] = cn;
            hout[gm*256 + jj] = sigm(zo)*tanhf(cn);
        }
    }
}

// ---------------- step t=0 elementwise (h-input = broadcast h1) ----------------
__global__ void k_cell0(const float* __restrict__ xw, float* __restrict__ hout,
                        float* __restrict__ cbuf)
{
    int gm = blockIdx.x, jj = threadIdx.x;
    float4 zx = *reinterpret_cast<const float4*>(&xw[(gm*4)*1024 + jj*4]);
    float4 zh = *reinterpret_cast<const float4*>(&g_hh1[jj*4]);
    float zi = zx.x + zh.x, zf = zx.y + zh.y, zg = zx.z + zh.z, zo = zx.w + zh.w;
    float cn = sigm(zf)*g_c1[jj] + sigm(zi)*tanhf(zg);
    cbuf[gm*256 + jj] = cn;
    hout[gm*256 + jj] = sigm(zo)*tanhf(cn);
}

// ---------------- tag + log_softmax ----------------
__global__ void tag_kernel(const float* __restrict__ h, const int* __restrict__ ids,
                           float* __restrict__ out, int M)
{
    __shared__ float As[32][20];
    __shared__ float Ws[32][256];
    __shared__ float red[16][16];
    __shared__ float rowmax[16], rowlse[16];
    float* stag = &Ws[0][0];

    int tid = threadIdx.x;
    int rg = tid >> 6;
    int cg = tid & 63;
    int m0 = blockIdx.x * 16;

    float acc[4][4];
    #pragma unroll
    for (int a = 0; a < 4; a++)
        #pragma unroll
        for (int b = 0; b < 4; b++) acc[a][b] = 0.f;

    for (int k0 = 0; k0 < 256; k0 += 32){
        #pragma unroll
        for (int q = 0; q < 2; q++){
            int e = tid + q*256;
            int m = e >> 5, kk = e & 31;
            int gm = m0 + m;
            As[kk][m] = (gm < M) ? h[gm*256 + k0 + kk] : 0.f;
        }
        #pragma unroll
        for (int q = 0; q < 8; q++){
            int e = tid + q*256;
            int kk = e >> 6, c4 = e & 63;
            *reinterpret_cast<float4*>(&Ws[kk][c4*4]) =
                *reinterpret_cast<const float4*>(&g_WcombHT[(k0+kk)*256 + c4*4]);
        }
        __syncthreads();
        #pragma unroll
        for (int kk = 0; kk < 32; kk++){
            float4 a = *reinterpret_cast<const float4*>(&As[kk][rg*4]);
            float4 b = *reinterpret_cast<const float4*>(&Ws[kk][cg*4]);
            acc[0][0] = fmaf(a.x, b.x, acc[0][0]); acc[0][1] = fmaf(a.x, b.y, acc[0][1]);
            acc[0][2] = fmaf(a.x, b.z, acc[0][2]); acc[0][3] = fmaf(a.x, b.w, acc[0][3]);
            acc[1][0] = fmaf(a.y, b.x, acc[1][0]); acc[1][1] = fmaf(a.y, b.y, acc[1][1]);
            acc[1][2] = fmaf(a.y, b.z, acc[1][2]); acc[1][3] = fmaf(a.y, b.w, acc[1][3]);
            acc[2][0] = fmaf(a.z, b.x, acc[2][0]); acc[2][1] = fmaf(a.z, b.y, acc[2][1]);
            acc[2][2] = fmaf(a.z, b.z, acc[2][2]); acc[2][3] = fmaf(a.z, b.w, acc[2][3]);
            acc[3][0] = fmaf(a.w, b.x, acc[3][0]); acc[3][1] = fmaf(a.w, b.y, acc[3][1]);
            acc[3][2] = fmaf(a.w, b.z, acc[3][2]); acc[3][3] = fmaf(a.w, b.w, acc[3][3]);
        }
        __syncthreads();
    }

    float4 bc = *reinterpret_cast<const float4*>(&g_bcomb[cg*4]);
    #pragma unroll
    for (int ri = 0; ri < 4; ri++){
        int r = rg*4 + ri;
        int gm = m0 + r;
        int id = (gm < M) ? ids[gm] : 0;
        float4 te = *reinterpret_cast<const float4*>(&g_tagE[id*256 + cg*4]);
        float4 v = make_float4(acc[ri][0]+te.x+bc.x, acc[ri][1]+te.y+bc.y,
                               acc[ri][2]+te.z+bc.z, acc[ri][3]+te.w+bc.w);
        *reinterpret_cast<float4*>(&stag[r*256 + cg*4]) = v;
    }
    __syncthreads();
    {
        int r = tid >> 4, s = tid & 15;
        float mx = -1e30f;
        #pragma unroll
        for (int q = 0; q < 16; q++) mx = fmaxf(mx, stag[r*256 + s*16 + q]);
        red[r][s] = mx;
    }
    __syncthreads();
    if (tid < 16){
        float mx = red[tid][0];
        #pragma unroll
        for (int s = 1; s < 16; s++) mx = fmaxf(mx, red[tid][s]);
        rowmax[tid] = mx;
    }
    __syncthreads();
    {
        int r = tid >> 4, s = tid & 15;
        float sm = 0.f, mx = rowmax[r];
        #pragma unroll
        for (int q = 0; q < 16; q++) sm += expf(stag[r*256 + s*16 + q] - mx);
        red[r][s] = sm;
    }
    __syncthreads();
    if (tid < 16){
        float sm = 0.f;
        #pragma unroll
        for (int s = 0; s < 16; s++) sm += red[tid][s];
        rowlse[tid] = logf(sm);
    }
    __syncthreads();
    #pragma unroll
    for (int q = 0; q < 16; q++){
        int e = tid + q*256;
        int r = e >> 8, i = e & 255;
        int gm = m0 + r;
        if (gm < M) out[gm*256 + i] = stag[r*256 + i] - rowmax[r] - rowlse[r];
    }
}

// ---------------- tail: levels 3..0, persistent ----------------
__device__ void dev_xw_tile(const float* __restrict__ child, int tile, int M4, float* sh)
{
    int mblk = tile >> 3, j0q = (tile & 7)*32, m0 = mblk*16;
    int tid = threadIdx.x, r = tid >> 4, tj = tid & 15;
    #pragma unroll
    for (int q = 0; q < 4; q++){
        int e = tid + q*256;
        int row = e >> 6, c4 = e & 63;
        int gm = m0 + row;
        float4 v = make_float4(0.f,0.f,0.f,0.f);
        if (gm < M4) v = *reinterpret_cast<const float4*>(&child[gm*256 + c4*4]);
        *reinterpret_cast<float4*>(&sh[row*264 + c4*4]) = v;
    }
    __syncthreads();
    int q0 = j0q + tj, q1 = q0 + 16;
    float4 acc0 = make_float4(0.f,0.f,0.f,0.f);
    float4 acc1 = make_float4(0.f,0.f,0.f,0.f);
    const float* w0 = g_WcatT + q0*4;
    const float* w1 = g_WcatT + q1*4;
    #pragma unroll 4
    for (int k = 0; k < 256; k++){
        float a = sh[r*264 + k];
        float4 b0 = *reinterpret_cast<const float4*>(&w0[k*1024]);
        float4 b1 = *reinterpret_cast<const float4*>(&w1[k*1024]);
        acc0.x = fmaf(a,b0.x,acc0.x); acc0.y = fmaf(a,b0.y,acc0.y);
        acc0.z = fmaf(a,b0.z,acc0.z); acc0.w = fmaf(a,b0.w,acc0.w);
        acc1.x = fmaf(a,b1.x,acc1.x); acc1.y = fmaf(a,b1.y,acc1.y);
        acc1.z = fmaf(a,b1.z,acc1.z); acc1.w = fmaf(a,b1.w,acc1.w);
    }
    int gm = m0 + r;
    if (gm < M4){
        float4 bz0 = *reinterpret_cast<const float4*>(&g_bzT[q0*4]);
        float4 bz1 = *reinterpret_cast<const float4*>(&g_bzT[q1*4]);
        *reinterpret_cast<float4*>(&g_xw[gm*1024 + q0*4]) =
            make_float4(acc0.x+bz0.x, acc0.y+bz0.y, acc0.z+bz0.z, acc0.w+bz0.w);
        *reinterpret_cast<float4*>(&g_xw[gm*1024 + q1*4]) =
            make_float4(acc1.x+bz1.x, acc1.y+bz1.y, acc1.z+bz1.z, acc1.w+bz1.w);
    }
    __syncthreads();
}

__device__ void dev_step_tile(const float* __restrict__ hin, float* __restrict__ hout,
                              const float* __restrict__ xwt, int first, int M,
                              int tile, float* sh)
{
    int mblk = tile >> 3, j0q = (tile & 7)*32, m0 = mblk*16;
    int tid = threadIdx.x, r = tid >> 4, tj = tid & 15;
    #pragma unroll
    for (int q = 0; q < 4; q++){
        int e = tid + q*256;
        int row = e >> 6, c4 = e & 63;
        int gm = m0 + row;
        float4 v = make_float4(0.f,0.f,0.f,0.f);
        if (gm < M)
            v = first ? *reinterpret_cast<const float4*>(&g_h1[c4*4])
                      : *reinterpret_cast<const float4*>(&hin[gm*256 + c4*4]);
        *reinterpret_cast<float4*>(&sh[row*264 + c4*4]) = v;
    }
    __syncthreads();
    int q0 = j0q + tj, q1 = q0 + 16;
    float4 acc0 = make_float4(0.f,0.f,0.f,0.f);
    float4 acc1 = make_float4(0.f,0.f,0.f,0.f);
    const float* whh = g_WcatT + 256*1024;
    const float* w0 = whh + q0*4;
    const float* w1 = whh + q1*4;
    #pragma unroll 4
    for (int k = 0; k < 256; k++){
        float a = sh[r*264 + k];
        float4 b0 = *reinterpret_cast<const float4*>(&w0[k*1024]);
        float4 b1 = *reinterpret_cast<const float4*>(&w1[k*1024]);
        acc0.x = fmaf(a,b0.x,acc0.x); acc0.y = fmaf(a,b0.y,acc0.y);
        acc0.z = fmaf(a,b0.z,acc0.z); acc0.w = fmaf(a,b0.w,acc0.w);
        acc1.x = fmaf(a,b1.x,acc1.x); acc1.y = fmaf(a,b1.y,acc1.y);
        acc1.z = fmaf(a,b1.z,acc1.z); acc1.w = fmaf(a,b1.w,acc1.w);
    }
    int gm = m0 + r;
    if (gm < M){
        const float* ad = xwt + gm*4096;
        float4 a0 = *reinterpret_cast<const float4*>(&ad[q0*4]);
        float4 a1 = *reinterpret_cast<const float4*>(&ad[q1*4]);
        {
            float zi = acc0.x+a0.x, zf = acc0.y+a0.y, zg = acc0.z+a0.z, zo = acc0.w+a0.w;
            float cold = first ? g_c1[q0] : g_c[gm*256 + q0];
            float cn = sigm(zf)*cold + sigm(zi)*tanhf(zg);
            g_c[gm*256 + q0] = cn;
            hout[gm*256 + q0] = sigm(zo)*tanhf(cn);
        }
        {
            float zi = acc1.x+a1.x, zf = acc1.y+a1.y, zg = acc1.z+a1.z, zo = acc1.w+a1.w;
            float cold = first ? g_c1[q1] : g_c[gm*256 + q1];
            float cn = sigm(zf)*cold + sigm(zi)*tanhf(zg);
            g_c[gm*256 + q1] = cn;
            hout[gm*256 + q1] = sigm(zo)*tanhf(cn);
        }
    }
    __syncthreads();
}

__device__ void dev_tag_tile(const float* __restrict__ h, const int* __restrict__ ids,
                             float* __restrict__ out, int M, int tile, float* sh)
{
    float* As = sh;
    float* Ws = sh + 640;
    float* red = sh + 640 + 8192;
    float* rowmax = red + 256;
    float* rowlse = rowmax + 16;
    float* stag = Ws;

    int tid = threadIdx.x;
    int rg = tid >> 6;
    int cg = tid & 63;
    int m0 = tile * 16;

    float acc[4][4];
    #pragma unroll
    for (int a = 0; a < 4; a++)
        #pragma unroll
        for (int b = 0; b < 4; b++) acc[a][b] = 0.f;

    for (int k0 = 0; k0 < 256; k0 += 32){
        #pragma unroll
        for (int q = 0; q < 2; q++){
            int e = tid + q*256;
            int m = e >> 5, kk = e & 31;
            int gm = m0 + m;
            As[kk*20 + m] = (gm < M) ? h[gm*256 + k0 + kk] : 0.f;
        }
        #pragma unroll
        for (int q = 0; q < 8; q++){
            int e = tid + q*256;
            int kk = e >> 6, c4 = e & 63;
            *reinterpret_cast<float4*>(&Ws[kk*256 + c4*4]) =
                *reinterpret_cast<const float4*>(&g_WcombHT[(k0+kk)*256 + c4*4]);
        }
        __syncthreads();
        #pragma unroll
        for (int kk = 0; kk < 32; kk++){
            float4 a = *reinterpret_cast<const float4*>(&As[kk*20 + rg*4]);
            float4 b = *reinterpret_cast<const float4*>(&Ws[kk*256 + cg*4]);
            acc[0][0] = fmaf(a.x, b.x, acc[0][0]); acc[0][1] = fmaf(a.x, b.y, acc[0][1]);
            acc[0][2] = fmaf(a.x, b.z, acc[0][2]); acc[0][3] = fmaf(a.x, b.w, acc[0][3]);
            acc[1][0] = fmaf(a.y, b.x, acc[1][0]); acc[1][1] = fmaf(a.y, b.y, acc[1][1]);
            acc[1][2] = fmaf(a.y, b.z, acc[1][2]); acc[1][3] = fmaf(a.y, b.w, acc[1][3]);
            acc[2][0] = fmaf(a.z, b.x, acc[2][0]); acc[2][1] = fmaf(a.z, b.y, acc[2][1]);
            acc[2][2] = fmaf(a.z, b.z, acc[2][2]); acc[2][3] = fmaf(a.z, b.w, acc[2][3]);
            acc[3][0] = fmaf(a.w, b.x, acc[3][0]); acc[3][1] = fmaf(a.w, b.y, acc[3][1]);
            acc[3][2] = fmaf(a.w, b.z, acc[3][2]); acc[3][3] = fmaf(a.w, b.w, acc[3][3]);
        }
        __syncthreads();
    }

    float4 bc = *reinterpret_cast<const float4*>(&g_bcomb[cg*4]);
    #pragma unroll
    for (int ri = 0; ri < 4; ri++){
        int r = rg*4 + ri;
        int gm = m0 + r;
        int id = (gm < M) ? ids[gm] : 0;
        float4 te = *reinterpret_cast<const float4*>(&g_tagE[id*256 + cg*4]);
        float4 v = make_float4(acc[ri][0]+te.x+bc.x, acc[ri][1]+te.y+bc.y,
                               acc[ri][2]+te.z+bc.z, acc[ri][3]+te.w+bc.w);
        *reinterpret_cast<float4*>(&stag[r*256 + cg*4]) = v;
    }
    __syncthreads();
    {
        int r = tid >> 4, s = tid & 15;
        float mx = -1e30f;
        #pragma unroll
        for (int q = 0; q < 16; q++) mx = fmaxf(mx, stag[r*256 + s*16 + q]);
        red[r*16 + s] = mx;
    }
    __syncthreads();
    if (tid < 16){
        float mx = red[tid*16];
        #pragma unroll
        for (int s = 1; s < 16; s++) mx = fmaxf(mx, red[tid*16 + s]);
        rowmax[tid] = mx;
    }
    __syncthreads();
    {
        int r = tid >> 4, s = tid & 15;
        float sm = 0.f, mx = rowmax[r];
        #pragma unroll
        for (int q = 0; q < 16; q++) sm += expf(stag[r*256 + s*16 + q] - mx);
        red[r*16 + s] = sm;
    }
    __syncthreads();
    if (tid < 16){
        float sm = 0.f;
        #pragma unroll
        for (int s = 0; s < 16; s++) sm += red[tid*16 + s];
        rowlse[tid] = logf(sm);
    }
    __syncthreads();
    #pragma unroll
    for (int q = 0; q < 16; q++){
        int e = tid + q*256;
        int r = e >> 8, i = e & 255;
        int gm = m0 + r;
        if (gm < M) out[gm*256 + i] = stag[r*256 + i] - rowmax[r] - rowlse[r];
    }
    __syncthreads();
}

__global__ void __launch_bounds__(256)
k_tail(const int* __restrict__ idents, float* __restrict__ outp)
{
    __shared__ __align__(16) float sh[640 + 8192 + 256 + 32];
    int cur = 0;
    float* ch[2];
    ch[0] = g_childB; ch[1] = g_childA;

    for (int l = 3; l >= 0; l--){
        int M = 1 << (2*l);
        int M4 = 4*M;
        int off = (M - 1)/3;
        {
            int nt = ((M4 + 15)/16)*8;
            for (int t = blockIdx.x; t < nt; t += NB)
                dev_xw_tile(ch[cur], t, M4, sh);
        }
        gridbar();
        for (int t4 = 0; t4 < 4; t4++){
            const float* hin = (t4 & 1) ? g_hA : g_hB;
            float* hout = (t4 & 1) ? g_hB : g_hA;
            int nt = ((M + 15)/16)*8;
            for (int t = blockIdx.x; t < nt; t += NB)
                dev_step_tile(hin, hout, g_xw + t4*1024, (t4==0)?1:0, M, t, sh);
            gridbar();
        }
        {
            float* o = (l == 0) ? outp : ch[cur ^ 1];
            int nt = (M + 15)/16;
            for (int t = blockIdx.x; t < nt; t += NB)
                dev_tag_tile(g_hB, idents + off, o, M, t, sh);
        }
        gridbar();
        cur ^= 1;
    }
}

// ---------------- host launcher ----------------
extern "C" void kernel_launch(void* const* d_in, const int* in_sizes, int n_in,
                              void* d_out, int out_size)
{
    const int*   idents    = (const int*)  d_in[0];
    const float* emb       = (const float*)d_in[1];
    const float* W_ih      = (const float*)d_in[2];
    const float* W_hh      = (const float*)d_in[3];
    const float* b_ih      = (const float*)d_in[4];
    const float* b_hh      = (const float*)d_in[5];
    const float* Wc        = (const float*)d_in[6];
    const float* bc        = (const float*)d_in[7];
    const float* Wt        = (const float*)d_in[8];
    const float* bt        = (const float*)d_in[9];
    const float* lstm_init = (const float*)d_in[10];
    float* out = (float*)d_out;
    (void)in_sizes; (void)n_in; (void)out_size;

    void* p;
    float *hA, *hB, *cbuf, *chA, *chB, *xw, *wcatT, *leafxW, *bzT, *h676, *c676;
    cudaGetSymbolAddress(&p, g_hA);     hA     = (float*)p;
    cudaGetSymbolAddress(&p, g_hB);     hB     = (float*)p;
    cudaGetSymbolAddress(&p, g_c);      cbuf   = (float*)p;
    cudaGetSymbolAddress(&p, g_childA); chA    = (float*)p;
    cudaGetSymbolAddress(&p, g_childB); chB    = (float*)p;
    cudaGetSymbolAddress(&p, g_xw);     xw     = (float*)p;
    cudaGetSymbolAddress(&p, g_WcatT);  wcatT  = (float*)p;
    cudaGetSymbolAddress(&p, g_leafxW); leafxW = (float*)p;
    cudaGetSymbolAddress(&p, g_bzT);    bzT    = (float*)p;
    cudaGetSymbolAddress(&p, g_h676);   h676   = (float*)p;
    cudaGetSymbolAddress(&p, g_c676);   c676   = (float*)p;
    const float* wih = wcatT;
    const float* whh = wcatT + 256*1024;

    // prologue (persistent, 2 launches)
    k_preA<<<NB, 256>>>(Wt, Wc, bc, bt, W_ih, W_hh, b_ih, b_hh, emb, lstm_init);
    k_preB<<<NB, 256>>>(W_ih, b_ih, b_hh);

    const int leaf_off = 21845;   // (4^8-1)/3
    // level 7 (M=16384): t=2 gather-step, t=3 step, tag -> childA
    simt_gemm<4><<<dim3(128,8), 256>>>(h676, hA, c676, cbuf, whh,
                                       idents + leaf_off, leafxW, 0, 16384);
    simt_gemm<2><<<dim3(128,8), 256>>>(hA, hB, cbuf, cbuf, whh,
                                       idents + leaf_off + 3, leafxW, 0, 16384);
    tag_kernel<<<1024, 256>>>(hB, idents + 5461, chA, 16384);

    // levels 6..4
    struct Lvl { int M; float* chin; float* chout; int off; };
    Lvl lv[3] = {
        {4096, chA, chB, 1365},
        {1024, chB, chA, 341},
        {256,  chA, chB, 85},
    };
    for (int li = 0; li < 3; li++){
        int M = lv[li].M;
        int M4 = 4*M;
        simt_gemm<0><<<dim3(M4/128,8), 256>>>(lv[li].chin, xw, nullptr, nullptr, wih,
                                              nullptr, bzT, 0, M4);
        k_cell0<<<M, 256>>>(xw, hA, cbuf);
        for (int t = 1; t < 4; t++){
            const float* hin = (t & 1) ? hA : hB;
            float* hout = (t & 1) ? hB : hA;
            simt_gemm<1><<<dim3(M/128,8), 256>>>(hin, hout, cbuf, cbuf, whh,
                                                 nullptr, xw, t, M);
        }
        tag_kernel<<<M/16, 256>>>(hB, idents + lv[li].off, lv[li].chout, M);
    }

    // tail: levels 3..0 (reads childB written by level-4 tag)
    k_tail<<<NB, 256>>>(idents, out);
}

// round 12
// speedup vs baseline: 1.0945x; 1.0945x over previous
#include <cuda_runtime.h>

// ---------------- scratch (device globals; allocation-free) ----------------
__device__ float g_hA[16384*256];
__device__ float g_hB[16384*256];
__device__ float g_c [16384*256];
__device__ float g_childA[16384*256];
__device__ float g_childB[4096*256];
__device__ float g_xw[16384*1024];
__device__ float g_WcatT[512*1024];     // [k][jj*4+g] (k<256: W_ih, else W_hh)
__device__ float g_Wcomb[256*512];
__device__ float g_WcombHT[256*256];
__device__ float g_bcomb[256];
__device__ float g_tagE[26*256];
__device__ float g_leafout[26*256];
__device__ float g_leafxW[26*1024];
__device__ float g_h1[256];
__device__ float g_c1[256];
__device__ float g_bzT[1024];
__device__ float g_hh1[1024];
__device__ float g_h676[676*256];
__device__ float g_c676[676*256];

// grid barrier state
__device__ int g_barcnt = 0;
__device__ volatile int g_bargen = 0;

__device__ __forceinline__ float sigm(float x){ return 1.0f/(1.0f+expf(-x)); }

#define NB 132

__device__ __forceinline__ void gridbar(){
    __syncthreads();
    if (threadIdx.x == 0){
        int g = g_bargen;
        __threadfence();
        if (atomicAdd(&g_barcnt, 1) == NB-1){
            g_barcnt = 0;
            __threadfence();
            g_bargen = g + 1;
        } else {
            while (g_bargen == g) { }
        }
    }
    __syncthreads();
    __threadfence();
}

// ---------------- prologue A ----------------
__global__ void __launch_bounds__(256)
k_preA(const float* __restrict__ Wt, const float* __restrict__ Wc,
       const float* __restrict__ bc, const float* __restrict__ bt,
       const float* __restrict__ W_ih, const float* __restrict__ W_hh,
       const float* __restrict__ b_ih, const float* __restrict__ b_hh,
       const float* __restrict__ emb, const float* __restrict__ lstm_init)
{
    __shared__ float sm[1280];
    int tid = threadIdx.x;

    for (int t = blockIdx.x; t < 2563; t += NB){
        if (t < 512){
            int idx = t*256 + tid;
            int i = idx >> 9, k = idx & 511;
            float s = 0.f;
            #pragma unroll 8
            for (int j = 0; j < 256; j++) s += Wt[i*256+j]*Wc[j*512+k];
            g_Wcomb[idx] = s;
        } else if (t == 512){
            float s = bt[tid];
            #pragma unroll 8
            for (int j = 0; j < 256; j++) s += Wt[tid*256+j]*bc[j];
            g_bcomb[tid] = s;
        } else if (t < 2561){
            int idx = (t-513)*256 + tid;
            int k = idx >> 10, col = idx & 1023;
            int jj = col >> 2, g = col & 3;
            int row = g*256 + jj;
            g_WcatT[idx] = (k < 256) ? W_ih[row*256 + k] : W_hh[row*256 + (k-256)];
        } else if (t == 2561){
            #pragma unroll
            for (int rr = 0; rr < 4; rr++){
                int idx = tid + rr*256;
                int jj = idx >> 2, g = idx & 3;
                g_bzT[idx] = b_ih[g*256+jj] + b_hh[g*256+jj];
            }
        } else {
            sm[tid] = lstm_init[tid];
            __syncthreads();
            #pragma unroll
            for (int rr = 0; rr < 4; rr++){
                int j = tid + rr*256;
                float s = b_ih[j] + b_hh[j];
                const float* w = &W_ih[j*256];
                #pragma unroll 8
                for (int k = 0; k < 256; k++) s += sm[k]*w[k];
                sm[256 + j] = s;
            }
            __syncthreads();
            float c = sigm(sm[256+tid]) * tanhf(sm[256+tid+512]);
            g_c1[tid] = c;
            g_h1[tid] = sigm(sm[256+tid+768]) * tanhf(c);
            __syncthreads();
        }
    }
    gridbar();
    for (int t = blockIdx.x; t < 286; t += NB){
        if (t < 256){
            int idx = t*256 + tid;
            int k = idx >> 8, i = idx & 255;
            g_WcombHT[idx] = g_Wcomb[i*512 + k];
        } else if (t < 282){
            int v = t - 256;
            sm[tid] = emb[v*256 + tid];
            __syncthreads();
            float s = 0.f;
            #pragma unroll 8
            for (int k = 0; k < 256; k++) s += sm[k]*g_Wcomb[tid*512 + 256 + k];
            g_tagE[v*256 + tid] = s;
            __syncthreads();
        } else {
            int col = (t-282)*256 + tid;
            sm[tid] = g_h1[tid];
            __syncthreads();
            const float* w = g_WcatT + 256*1024;
            float s = 0.f;
            #pragma unroll 8
            for (int k = 0; k < 256; k++) s += sm[k]*w[k*1024 + col];
            g_hh1[col] = s;
            __syncthreads();
        }
    }
}

// ---------------- prologue B: leafout | leafxw | 676 states ----------------
__global__ void __launch_bounds__(256)
k_preB(const float* __restrict__ W_ih, const float* __restrict__ b_ih,
       const float* __restrict__ b_hh)
{
    __shared__ float sh[16*264];
    __shared__ int rmapS[16], aidxS[16];
    int tid = threadIdx.x;

    for (int t = blockIdx.x; t < 26; t += NB){
        int v = t, i = tid;
        float* h1s = sh;
        float* red = sh + 256;
        h1s[i] = g_h1[i];
        __syncthreads();
        float s = g_tagE[v*256+i] + g_bcomb[i];
        #pragma unroll 8
        for (int k = 0; k < 256; k++) s += h1s[k]*g_Wcomb[i*512 + k];
        red[i] = s; __syncthreads();
        for (int st = 128; st > 0; st >>= 1){ if (i < st) red[i] = fmaxf(red[i], red[i+st]); __syncthreads(); }
        float mx = red[0]; __syncthreads();
        red[i] = expf(s - mx); __syncthreads();
        for (int st = 128; st > 0; st >>= 1){ if (i < st) red[i] += red[i+st]; __syncthreads(); }
        float lse = mx + logf(red[0]);
        g_leafout[v*256 + i] = s - lse;
        __syncthreads();
    }
    gridbar();
    for (int t = blockIdx.x; t < 104; t += NB){
        int v = t >> 2, jb = t & 3;
        int c = jb*256 + tid;
        int jj = c >> 2, g = c & 3;
        int row = g*256 + jj;
        sh[tid] = g_leafout[v*256 + tid];
        __syncthreads();
        float s = b_ih[row] + b_hh[row];
        #pragma unroll 8
        for (int k = 0; k < 256; k++) s += sh[k]*W_ih[row*256 + k];
        g_leafxW[v*1024 + c] = s;
        __syncthreads();
    }
    gridbar();
    const float* whh = g_WcatT + 256*1024;
    for (int t = blockIdx.x; t < 344; t += NB){
        int mblk = t >> 3, j0q = (t & 7)*32, m0 = mblk*16;
        const int M = 676;
        int r = tid >> 4, tj = tid & 15;
        if (tid < 16){
            int gm = m0 + tid;
            int rr = 0, a = 0;
            if (gm < M){ rr = gm/26; a = gm - rr*26; }
            rmapS[tid] = rr; aidxS[tid] = a;
        }
        __syncthreads();
        #pragma unroll
        for (int q = 0; q < 16; q++){
            int e = tid + q*256;
            int row = e >> 8, k = e & 255;
            int i0 = rmapS[row];
            float4 zh = *reinterpret_cast<const float4*>(&g_hh1[k*4]);
            float4 zl = *reinterpret_cast<const float4*>(&g_leafxW[i0*1024 + k*4]);
            float cz = sigm(zh.y+zl.y)*g_c1[k] + sigm(zh.x+zl.x)*tanhf(zh.z+zl.z);
            sh[row*264 + k] = sigm(zh.w+zl.w)*tanhf(cz);
        }
        __syncthreads();
        int q0 = j0q + tj, q1 = q0 + 16;
        float4 acc0 = make_float4(0.f,0.f,0.f,0.f);
        float4 acc1 = make_float4(0.f,0.f,0.f,0.f);
        const float* w0 = whh + q0*4;
        const float* w1 = whh + q1*4;
        #pragma unroll 4
        for (int k = 0; k < 256; k++){
            float a = sh[r*264 + k];
            float4 b0 = *reinterpret_cast<const float4*>(&w0[k*1024]);
            float4 b1 = *reinterpret_cast<const float4*>(&w1[k*1024]);
            acc0.x = fmaf(a,b0.x,acc0.x); acc0.y = fmaf(a,b0.y,acc0.y);
            acc0.z = fmaf(a,b0.z,acc0.z); acc0.w = fmaf(a,b0.w,acc0.w);
            acc1.x = fmaf(a,b1.x,acc1.x); acc1.y = fmaf(a,b1.y,acc1.y);
            acc1.z = fmaf(a,b1.z,acc1.z); acc1.w = fmaf(a,b1.w,acc1.w);
        }
        int gm = m0 + r;
        if (gm < M){
            const float* ad = g_leafxW + aidxS[r]*1024;
            float4 a0 = *reinterpret_cast<const float4*>(&ad[q0*4]);
            float4 a1 = *reinterpret_cast<const float4*>(&ad[q1*4]);
            float4 zh0 = *reinterpret_cast<const float4*>(&g_hh1[q0*4]);
            float4 zl0 = *reinterpret_cast<const float4*>(&g_leafxW[rmapS[r]*1024 + q0*4]);
            float cold0 = sigm(zh0.y+zl0.y)*g_c1[q0] + sigm(zh0.x+zl0.x)*tanhf(zh0.z+zl0.z);
            float4 zh1 = *reinterpret_cast<const float4*>(&g_hh1[q1*4]);
            float4 zl1 = *reinterpret_cast<const float4*>(&g_leafxW[rmapS[r]*1024 + q1*4]);
            float cold1 = sigm(zh1.y+zl1.y)*g_c1[q1] + sigm(zh1.x+zl1.x)*tanhf(zh1.z+zl1.z);
            {
                float zi = acc0.x+a0.x, zf = acc0.y+a0.y, zg = acc0.z+a0.z, zo = acc0.w+a0.w;
                float cn = sigm(zf)*cold0 + sigm(zi)*tanhf(zg);
                g_c676[gm*256 + q0] = cn;
                g_h676[gm*256 + q0] = sigm(zo)*tanhf(cn);
            }
            {
                float zi = acc1.x+a1.x, zf = acc1.y+a1.y, zg = acc1.z+a1.z, zo = acc1.w+a1.w;
                float cn = sigm(zf)*cold1 + sigm(zi)*tanhf(zg);
                g_c676[gm*256 + q1] = cn;
                g_h676[gm*256 + q1] = sigm(zo)*tanhf(cn);
            }
        }
        __syncthreads();
    }
}

// ---------------- SIMT GEMM v4: 64x128 tile, 8x4 thread tile, double-buffered ----------------
// Block: 64 rows x 32 quad-cols (=128 cols), 256 threads, acc[8][4].
// Register-prefetch next k-slab, STS after compute, one sync per iter.
// MODE 0: xw: A=child rows, out xw[gm*1024+col] = acc + bzT[col]
// MODE 1: h-step: A=hin[gm], add=xw[(gm*4+t)], cell w/ cin->cout
// MODE 2: L7 t=3: A=hin[gm], add=leafxW[ids[gm*4]], cell
// MODE 4: L7 t=2: A=h676[id0*26+id1], add=leafxW[id2], cold=c676[rmap]
template<int MODE>
__global__ void __launch_bounds__(256)
simt_gemm(const float* __restrict__ hin, float* __restrict__ hout,
          const float* __restrict__ cin, float* __restrict__ cout,
          const float* __restrict__ WT,
          const int* __restrict__ ids,
          const float* __restrict__ addbase,
          int t, int M)
{
    __shared__ float As[2][16][72];
    __shared__ float Ws[2][16][128];
    __shared__ int rmap[64], aidx[64];
    int tid = threadIdx.x;
    int tj = tid & 31;
    int tm = tid >> 5;
    int m0 = blockIdx.x * 64;
    int j0 = blockIdx.y * 32;

    if (MODE == 2 || MODE == 4){
        if (tid < 64){
            int gm = m0 + tid;
            int r = 0, a = 0;
            if (gm < M){
                if (MODE == 2){ r = gm; a = ids[gm*4]; }
                else { int i0 = ids[gm*4], i1 = ids[gm*4+1]; a = ids[gm*4+2]; r = i0*26 + i1; }
            }
            rmap[tid] = r; aidx[tid] = a;
        }
        __syncthreads();
    }

    // per-thread fixed load coordinates
    int am0 = tid >> 4, akk = tid & 15;          // A part 0: m=am0, m2=am0+... (q in {0..3}: m = (tid+q*256)>>4)
    int bkk = tid >> 5, bc4 = tid & 31;          // B: q in {0,1}

    float aR[4];
    float4 bR[2];

    auto ldA = [&](int k0){
        #pragma unroll
        for (int q = 0; q < 4; q++){
            int m = am0 + q*16;
            int gm = m0 + m;
            float v = 0.f;
            if (gm < M){
                int k = k0 + akk;
                if (MODE == 4) v = hin[rmap[m]*256 + k];
                else           v = hin[gm*256 + k];
            }
            aR[q] = v;
        }
    };
    auto ldB = [&](int k0){
        #pragma unroll
        for (int q = 0; q < 2; q++){
            bR[q] = *reinterpret_cast<const float4*>(&WT[(k0 + bkk + q*8)*1024 + j0*4 + bc4*4]);
        }
    };
    auto stAB = [&](int buf){
        #pragma unroll
        for (int q = 0; q < 4; q++) As[buf][akk][am0 + q*16] = aR[q];
        #pragma unroll
        for (int q = 0; q < 2; q++)
            *reinterpret_cast<float4*>(&Ws[buf][bkk + q*8][bc4*4]) = bR[q];
    };

    float acc[8][4];
    #pragma unroll
    for (int a = 0; a < 8; a++)
        #pragma unroll
        for (int b = 0; b < 4; b++) acc[a][b] = 0.f;

    ldA(0); ldB(0);
    stAB(0);
    __syncthreads();

    for (int it = 0; it < 16; it++){
        int buf = it & 1;
        if (it < 15){ ldA((it+1)*16); ldB((it+1)*16); }
        #pragma unroll
        for (int kk = 0; kk < 16; kk++){
            float4 b  = *reinterpret_cast<const float4*>(&Ws[buf][kk][tj*4]);
            float4 a0 = *reinterpret_cast<const float4*>(&As[buf][kk][tm*8]);
            float4 a1 = *reinterpret_cast<const float4*>(&As[buf][kk][tm*8+4]);
            acc[0][0] = fmaf(a0.x, b.x, acc[0][0]); acc[0][1] = fmaf(a0.x, b.y, acc[0][1]);
            acc[0][2] = fmaf(a0.x, b.z, acc[0][2]); acc[0][3] = fmaf(a0.x, b.w, acc[0][3]);
            acc[1][0] = fmaf(a0.y, b.x, acc[1][0]); acc[1][1] = fmaf(a0.y, b.y, acc[1][1]);
            acc[1][2] = fmaf(a0.y, b.z, acc[1][2]); acc[1][3] = fmaf(a0.y, b.w, acc[1][3]);
            acc[2][0] = fmaf(a0.z, b.x, acc[2][0]); acc[2][1] = fmaf(a0.z, b.y, acc[2][1]);
            acc[2][2] = fmaf(a0.z, b.z, acc[2][2]); acc[2][3] = fmaf(a0.z, b.w, acc[2][3]);
            acc[3][0] = fmaf(a0.w, b.x, acc[3][0]); acc[3][1] = fmaf(a0.w, b.y, acc[3][1]);
            acc[3][2] = fmaf(a0.w, b.z, acc[3][2]); acc[3][3] = fmaf(a0.w, b.w, acc[3][3]);
            acc[4][0] = fmaf(a1.x, b.x, acc[4][0]); acc[4][1] = fmaf(a1.x, b.y, acc[4][1]);
            acc[4][2] = fmaf(a1.x, b.z, acc[4][2]); acc[4][3] = fmaf(a1.x, b.w, acc[4][3]);
            acc[5][0] = fmaf(a1.y, b.x, acc[5][0]); acc[5][1] = fmaf(a1.y, b.y, acc[5][1]);
            acc[5][2] = fmaf(a1.y, b.z, acc[5][2]); acc[5][3] = fmaf(a1.y, b.w, acc[5][3]);
            acc[6][0] = fmaf(a1.z, b.x, acc[6][0]); acc[6][1] = fmaf(a1.z, b.y, acc[6][1]);
            acc[6][2] = fmaf(a1.z, b.z, acc[6][2]); acc[6][3] = fmaf(a1.z, b.w, acc[6][3]);
            acc[7][0] = fmaf(a1.w, b.x, acc[7][0]); acc[7][1] = fmaf(a1.w, b.y, acc[7][1]);
            acc[7][2] = fmaf(a1.w, b.z, acc[7][2]); acc[7][3] = fmaf(a1.w, b.w, acc[7][3]);
        }
        if (it < 15) stAB(buf ^ 1);
        __syncthreads();
    }

    int jj = j0 + tj;
    #pragma unroll
    for (int mi = 0; mi < 8; mi++){
        int m = tm*8 + mi;
        int gm = m0 + m;
        if (gm >= M) continue;
        float zi = acc[mi][0], zf = acc[mi][1], zg = acc[mi][2], zo = acc[mi][3];
        if (MODE == 0){
            float4 bz = *reinterpret_cast<const float4*>(&addbase[jj*4]);
            float4 v = make_float4(zi+bz.x, zf+bz.y, zg+bz.z, zo+bz.w);
            *reinterpret_cast<float4*>(&hout[gm*1024 + jj*4]) = v;
        } else {
            const float* ad;
            float cold;
            if (MODE == 1){
                ad = addbase + (gm*4 + t)*1024;
                cold = cin[gm*256 + jj];
            } else if (MODE == 2){
                ad = addbase + aidx[m]*1024;
                cold = cin[gm*256 + jj];
            } else {
                ad = addbase + aidx[m]*1024;
                cold = cin[rmap[m]*256 + jj];
            }
            float4 a4 = *reinterpret_cast<const float4*>(&ad[jj*4]);
            zi += a4.x; zf += a4.y; zg += a4.z; zo += a4.w;
            float cn = sigm(zf)*cold + sigm(zi)*tanhf(zg);
            cout[gm*256 + jj] = cn;
            hout[gm*256 + jj] = sigm(zo)*tanhf(cn);
        }
    }
}

// ---------------- step t=0 elementwise (h-input = broadcast h1) ----------------
__global__ void k_cell0(const float* __restrict__ xw, float* __restrict__ hout,
                        float* __restrict__ cbuf)
{
    int gm = blockIdx.x, jj = threadIdx.x;
    float4 zx = *reinterpret_cast<const float4*>(&xw[(gm*4)*1024 + jj*4]);
    float4 zh = *reinterpret_cast<const float4*>(&g_hh1[jj*4]);
    float zi = zx.x + zh.x, zf = zx.y + zh.y, zg = zx.z + zh.z, zo = zx.w + zh.w;
    float cn = sigm(zf)*g_c1[jj] + sigm(zi)*tanhf(zg);
    cbuf[gm*256 + jj] = cn;
    hout[gm*256 + jj] = sigm(zo)*tanhf(cn);
}

// ---------------- tag + log_softmax ----------------
__global__ void tag_kernel(const float* __restrict__ h, const int* __restrict__ ids,
                           float* __restrict__ out, int M)
{
    __shared__ float As[32][20];
    __shared__ float Ws[32][256];
    __shared__ float red[16][16];
    __shared__ float rowmax[16], rowlse[16];
    float* stag = &Ws[0][0];

    int tid = threadIdx.x;
    int rg = tid >> 6;
    int cg = tid & 63;
    int m0 = blockIdx.x * 16;

    float acc[4][4];
    #pragma unroll
    for (int a = 0; a < 4; a++)
        #pragma unroll
        for (int b = 0; b < 4; b++) acc[a][b] = 0.f;

    for (int k0 = 0; k0 < 256; k0 += 32){
        #pragma unroll
        for (int q = 0; q < 2; q++){
            int e = tid + q*256;
            int m = e >> 5, kk = e & 31;
            int gm = m0 + m;
            As[kk][m] = (gm < M) ? h[gm*256 + k0 + kk] : 0.f;
        }
        #pragma unroll
        for (int q = 0; q < 8; q++){
            int e = tid + q*256;
            int kk = e >> 6, c4 = e & 63;
            *reinterpret_cast<float4*>(&Ws[kk][c4*4]) =
                *reinterpret_cast<const float4*>(&g_WcombHT[(k0+kk)*256 + c4*4]);
        }
        __syncthreads();
        #pragma unroll
        for (int kk = 0; kk < 32; kk++){
            float4 a = *reinterpret_cast<const float4*>(&As[kk][rg*4]);
            float4 b = *reinterpret_cast<const float4*>(&Ws[kk][cg*4]);
            acc[0][0] = fmaf(a.x, b.x, acc[0][0]); acc[0][1] = fmaf(a.x, b.y, acc[0][1]);
            acc[0][2] = fmaf(a.x, b.z, acc[0][2]); acc[0][3] = fmaf(a.x, b.w, acc[0][3]);
            acc[1][0] = fmaf(a.y, b.x, acc[1][0]); acc[1][1] = fmaf(a.y, b.y, acc[1][1]);
            acc[1][2] = fmaf(a.y, b.z, acc[1][2]); acc[1][3] = fmaf(a.y, b.w, acc[1][3]);
            acc[2][0] = fmaf(a.z, b.x, acc[2][0]); acc[2][1] = fmaf(a.z, b.y, acc[2][1]);
            acc[2][2] = fmaf(a.z, b.z, acc[2][2]); acc[2][3] = fmaf(a.z, b.w, acc[2][3]);
            acc[3][0] = fmaf(a.w, b.x, acc[3][0]); acc[3][1] = fmaf(a.w, b.y, acc[3][1]);
            acc[3][2] = fmaf(a.w, b.z, acc[3][2]); acc[3][3] = fmaf(a.w, b.w, acc[3][3]);
        }
        __syncthreads();
    }

    float4 bc = *reinterpret_cast<const float4*>(&g_bcomb[cg*4]);
    #pragma unroll
    for (int ri = 0; ri < 4; ri++){
        int r = rg*4 + ri;
        int gm = m0 + r;
        int id = (gm < M) ? ids[gm] : 0;
        float4 te = *reinterpret_cast<const float4*>(&g_tagE[id*256 + cg*4]);
        float4 v = make_float4(acc[ri][0]+te.x+bc.x, acc[ri][1]+te.y+bc.y,
                               acc[ri][2]+te.z+bc.z, acc[ri][3]+te.w+bc.w);
        *reinterpret_cast<float4*>(&stag[r*256 + cg*4]) = v;
    }
    __syncthreads();
    {
        int r = tid >> 4, s = tid & 15;
        float mx = -1e30f;
        #pragma unroll
        for (int q = 0; q < 16; q++) mx = fmaxf(mx, stag[r*256 + s*16 + q]);
        red[r][s] = mx;
    }
    __syncthreads();
    if (tid < 16){
        float mx = red[tid][0];
        #pragma unroll
        for (int s = 1; s < 16; s++) mx = fmaxf(mx, red[tid][s]);
        rowmax[tid] = mx;
    }
    __syncthreads();
    {
        int r = tid >> 4, s = tid & 15;
        float sm = 0.f, mx = rowmax[r];
        #pragma unroll
        for (int q = 0; q < 16; q++) sm += expf(stag[r*256 + s*16 + q] - mx);
        red[r][s] = sm;
    }
    __syncthreads();
    if (tid < 16){
        float sm = 0.f;
        #pragma unroll
        for (int s = 0; s < 16; s++) sm += red[tid][s];
        rowlse[tid] = logf(sm);
    }
    __syncthreads();
    #pragma unroll
    for (int q = 0; q < 16; q++){
        int e = tid + q*256;
        int r = e >> 8, i = e & 255;
        int gm = m0 + r;
        if (gm < M) out[gm*256 + i] = stag[r*256 + i] - rowmax[r] - rowlse[r];
    }
}

// ---------------- tail: levels 3..0, persistent ----------------
__device__ void dev_xw_tile(const float* __restrict__ child, int tile, int M4, float* sh)
{
    int mblk = tile >> 3, j0q = (tile & 7)*32, m0 = mblk*16;
    int tid = threadIdx.x, r = tid >> 4, tj = tid & 15;
    #pragma unroll
    for (int q = 0; q < 4; q++){
        int e = tid + q*256;
        int row = e >> 6, c4 = e & 63;
        int gm = m0 + row;
        float4 v = make_float4(0.f,0.f,0.f,0.f);
        if (gm < M4) v = *reinterpret_cast<const float4*>(&child[gm*256 + c4*4]);
        *reinterpret_cast<float4*>(&sh[row*264 + c4*4]) = v;
    }
    __syncthreads();
    int q0 = j0q + tj, q1 = q0 + 16;
    float4 acc0 = make_float4(0.f,0.f,0.f,0.f);
    float4 acc1 = make_float4(0.f,0.f,0.f,0.f);
    const float* w0 = g_WcatT + q0*4;
    const float* w1 = g_WcatT + q1*4;
    #pragma unroll 4
    for (int k = 0; k < 256; k++){
        float a = sh[r*264 + k];
        float4 b0 = *reinterpret_cast<const float4*>(&w0[k*1024]);
        float4 b1 = *reinterpret_cast<const float4*>(&w1[k*1024]);
        acc0.x = fmaf(a,b0.x,acc0.x); acc0.y = fmaf(a,b0.y,acc0.y);
        acc0.z = fmaf(a,b0.z,acc0.z); acc0.w = fmaf(a,b0.w,acc0.w);
        acc1.x = fmaf(a,b1.x,acc1.x); acc1.y = fmaf(a,b1.y,acc1.y);
        acc1.z = fmaf(a,b1.z,acc1.z); acc1.w = fmaf(a,b1.w,acc1.w);
    }
    int gm = m0 + r;
    if (gm < M4){
        float4 bz0 = *reinterpret_cast<const float4*>(&g_bzT[q0*4]);
        float4 bz1 = *reinterpret_cast<const float4*>(&g_bzT[q1*4]);
        *reinterpret_cast<float4*>(&g_xw[gm*1024 + q0*4]) =
            make_float4(acc0.x+bz0.x, acc0.y+bz0.y, acc0.z+bz0.z, acc0.w+bz0.w);
        *reinterpret_cast<float4*>(&g_xw[gm*1024 + q1*4]) =
            make_float4(acc1.x+bz1.x, acc1.y+bz1.y, acc1.z+bz1.z, acc1.w+bz1.w);
    }
    __syncthreads();
}

__device__ void dev_step_tile(const float* __restrict__ hin, float* __restrict__ hout,
                              const float* __restrict__ xwt, int first, int M,
                              int tile, float* sh)
{
    int mblk = tile >> 3, j0q = (tile & 7)*32, m0 = mblk*16;
    int tid = threadIdx.x, r = tid >> 4, tj = tid & 15;
    #pragma unroll
    for (int q = 0; q < 4; q++){
        int e = tid + q*256;
        int row = e >> 6, c4 = e & 63;
        int gm = m0 + row;
        float4 v = make_float4(0.f,0.f,0.f,0.f);
        if (gm < M)
            v = first ? *reinterpret_cast<const float4*>(&g_h1[c4*4])
                      : *reinterpret_cast<const float4*>(&hin[gm*256 + c4*4]);
        *reinterpret_cast<float4*>(&sh[row*264 + c4*4]) = v;
    }
    __syncthreads();
    int q0 = j0q + tj, q1 = q0 + 16;
    float4 acc0 = make_float4(0.f,0.f,0.f,0.f);
    float4 acc1 = make_float4(0.f,0.f,0.f,0.f);
    const float* whh = g_WcatT + 256*1024;
    const float* w0 = whh + q0*4;
    const float* w1 = whh + q1*4;
    #pragma unroll 4
    for (int k = 0; k < 256; k++){
        float a = sh[r*264 + k];
        float4 b0 = *reinterpret_cast<const float4*>(&w0[k*1024]);
        float4 b1 = *reinterpret_cast<const float4*>(&w1[k*1024]);
        acc0.x = fmaf(a,b0.x,acc0.x); acc0.y = fmaf(a,b0.y,acc0.y);
        acc0.z = fmaf(a,b0.z,acc0.z); acc0.w = fmaf(a,b0.w,acc0.w);
        acc1.x = fmaf(a,b1.x,acc1.x); acc1.y = fmaf(a,b1.y,acc1.y);
        acc1.z = fmaf(a,b1.z,acc1.z); acc1.w = fmaf(a,b1.w,acc1.w);
    }
    int gm = m0 + r;
    if (gm < M){
        const float* ad = xwt + gm*4096;
        float4 a0 = *reinterpret_cast<const float4*>(&ad[q0*4]);
        float4 a1 = *reinterpret_cast<const float4*>(&ad[q1*4]);
        {
            float zi = acc0.x+a0.x, zf = acc0.y+a0.y, zg = acc0.z+a0.z, zo = acc0.w+a0.w;
            float cold = first ? g_c1[q0] : g_c[gm*256 + q0];
            float cn = sigm(zf)*cold + sigm(zi)*tanhf(zg);
            g_c[gm*256 + q0] = cn;
            hout[gm*256 + q0] = sigm(zo)*tanhf(cn);
        }
        {
            float zi = acc1.x+a1.x, zf = acc1.y+a1.y, zg = acc1.z+a1.z, zo = acc1.w+a1.w;
            float cold = first ? g_c1[q1] : g_c[gm*256 + q1];
            float cn = sigm(zf)*cold + sigm(zi)*tanhf(zg);
            g_c[gm*256 + q1] = cn;
            hout[gm*256 + q1] = sigm(zo)*tanhf(cn);
        }
    }
    __syncthreads();
}

__device__ void dev_tag_tile(const float* __restrict__ h, const int* __restrict__ ids,
                             float* __restrict__ out, int M, int tile, float* sh)
{
    float* As = sh;
    float* Ws = sh + 640;
    float* red = sh + 640 + 8192;
    float* rowmax = red + 256;
    float* rowlse = rowmax + 16;
    float* stag = Ws;

    int tid = threadIdx.x;
    int rg = tid >> 6;
    int cg = tid & 63;
    int m0 = tile * 16;

    float acc[4][4];
    #pragma unroll
    for (int a = 0; a < 4; a++)
        #pragma unroll
        for (int b = 0; b < 4; b++) acc[a][b] = 0.f;

    for (int k0 = 0; k0 < 256; k0 += 32){
        #pragma unroll
        for (int q = 0; q < 2; q++){
            int e = tid + q*256;
            int m = e >> 5, kk = e & 31;
            int gm = m0 + m;
            As[kk*20 + m] = (gm < M) ? h[gm*256 + k0 + kk] : 0.f;
        }
        #pragma unroll
        for (int q = 0; q < 8; q++){
            int e = tid + q*256;
            int kk = e >> 6, c4 = e & 63;
            *reinterpret_cast<float4*>(&Ws[kk*256 + c4*4]) =
                *reinterpret_cast<const float4*>(&g_WcombHT[(k0+kk)*256 + c4*4]);
        }
        __syncthreads();
        #pragma unroll
        for (int kk = 0; kk < 32; kk++){
            float4 a = *reinterpret_cast<const float4*>(&As[kk*20 + rg*4]);
            float4 b = *reinterpret_cast<const float4*>(&Ws[kk*256 + cg*4]);
            acc[0][0] = fmaf(a.x, b.x, acc[0][0]); acc[0][1] = fmaf(a.x, b.y, acc[0][1]);
            acc[0][2] = fmaf(a.x, b.z, acc[0][2]); acc[0][3] = fmaf(a.x, b.w, acc[0][3]);
            acc[1][0] = fmaf(a.y, b.x, acc[1][0]); acc[1][1] = fmaf(a.y, b.y, acc[1][1]);
            acc[1][2] = fmaf(a.y, b.z, acc[1][2]); acc[1][3] = fmaf(a.y, b.w, acc[1][3]);
            acc[2][0] = fmaf(a.z, b.x, acc[2][0]); acc[2][1] = fmaf(a.z, b.y, acc[2][1]);
            acc[2][2] = fmaf(a.z, b.z, acc[2][2]); acc[2][3] = fmaf(a.z, b.w, acc[2][3]);
            acc[3][0] = fmaf(a.w, b.x, acc[3][0]); acc[3][1] = fmaf(a.w, b.y, acc[3][1]);
            acc[3][2] = fmaf(a.w, b.z, acc[3][2]); acc[3][3] = fmaf(a.w, b.w, acc[3][3]);
        }
        __syncthreads();
    }

    float4 bc = *reinterpret_cast<const float4*>(&g_bcomb[cg*4]);
    #pragma unroll
    for (int ri = 0; ri < 4; ri++){
        int r = rg*4 + ri;
        int gm = m0 + r;
        int id = (gm < M) ? ids[gm] : 0;
        float4 te = *reinterpret_cast<const float4*>(&g_tagE[id*256 + cg*4]);
        float4 v = make_float4(acc[ri][0]+te.x+bc.x, acc[ri][1]+te.y+bc.y,
                               acc[ri][2]+te.z+bc.z, acc[ri][3]+te.w+bc.w);
        *reinterpret_cast<float4*>(&stag[r*256 + cg*4]) = v;
    }
    __syncthreads();
    {
        int r = tid >> 4, s = tid & 15;
        float mx = -1e30f;
        #pragma unroll
        for (int q = 0; q < 16; q++) mx = fmaxf(mx, stag[r*256 + s*16 + q]);
        red[r*16 + s] = mx;
    }
    __syncthreads();
    if (tid < 16){
        float mx = red[tid*16];
        #pragma unroll
        for (int s = 1; s < 16; s++) mx = fmaxf(mx, red[tid*16 + s]);
        rowmax[tid] = mx;
    }
    __syncthreads();
    {
        int r = tid >> 4, s = tid & 15;
        float sm = 0.f, mx = rowmax[r];
        #pragma unroll
        for (int q = 0; q < 16; q++) sm += expf(stag[r*256 + s*16 + q] - mx);
        red[r*16 + s] = sm;
    }
    __syncthreads();
    if (tid < 16){
        float sm = 0.f;
        #pragma unroll
        for (int s = 0; s < 16; s++) sm += red[tid*16 + s];
        rowlse[tid] = logf(sm);
    }
    __syncthreads();
    #pragma unroll
    for (int q = 0; q < 16; q++){
        int e = tid + q*256;
        int r = e >> 8, i = e & 255;
        int gm = m0 + r;
        if (gm < M) out[gm*256 + i] = stag[r*256 + i] - rowmax[r] - rowlse[r];
    }
    __syncthreads();
}

__global__ void __launch_bounds__(256)
k_tail(const int* __restrict__ idents, float* __restrict__ outp)
{
    __shared__ __align__(16) float sh[640 + 8192 + 256 + 32];
    int cur = 0;
    float* ch[2];
    ch[0] = g_childB; ch[1] = g_childA;

    for (int l = 3; l >= 0; l--){
        int M = 1 << (2*l);
        int M4 = 4*M;
        int off = (M - 1)/3;
        {
            int nt = ((M4 + 15)/16)*8;
            for (int t = blockIdx.x; t < nt; t += NB)
                dev_xw_tile(ch[cur], t, M4, sh);
        }
        gridbar();
        for (int t4 = 0; t4 < 4; t4++){
            const float* hin = (t4 & 1) ? g_hA : g_hB;
            float* hout = (t4 & 1) ? g_hB : g_hA;
            int nt = ((M + 15)/16)*8;
            for (int t = blockIdx.x; t < nt; t += NB)
                dev_step_tile(hin, hout, g_xw + t4*1024, (t4==0)?1:0, M, t, sh);
            gridbar();
        }
        {
            float* o = (l == 0) ? outp : ch[cur ^ 1];
            int nt = (M + 15)/16;
            for (int t = blockIdx.x; t < nt; t += NB)
                dev_tag_tile(g_hB, idents + off, o, M, t, sh);
        }
        gridbar();
        cur ^= 1;
    }
}

// ---------------- host launcher ----------------
extern "C" void kernel_launch(void* const* d_in, const int* in_sizes, int n_in,
                              void* d_out, int out_size)
{
    const int*   idents    = (const int*)  d_in[0];
    const float* emb       = (const float*)d_in[1];
    const float* W_ih      = (const float*)d_in[2];
    const float* W_hh      = (const float*)d_in[3];
    const float* b_ih      = (const float*)d_in[4];
    const float* b_hh      = (const float*)d_in[5];
    const float* Wc        = (const float*)d_in[6];
    const float* bc        = (const float*)d_in[7];
    const float* Wt        = (const float*)d_in[8];
    const float* bt        = (const float*)d_in[9];
    const float* lstm_init = (const float*)d_in[10];
    float* out = (float*)d_out;
    (void)in_sizes; (void)n_in; (void)out_size;

    void* p;
    float *hA, *hB, *cbuf, *chA, *chB, *xw, *wcatT, *leafxW, *bzT, *h676, *c676;
    cudaGetSymbolAddress(&p, g_hA);     hA     = (float*)p;
    cudaGetSymbolAddress(&p, g_hB);     hB     = (float*)p;
    cudaGetSymbolAddress(&p, g_c);      cbuf   = (float*)p;
    cudaGetSymbolAddress(&p, g_childA); chA    = (float*)p;
    cudaGetSymbolAddress(&p, g_childB); chB    = (float*)p;
    cudaGetSymbolAddress(&p, g_xw);     xw     = (float*)p;
    cudaGetSymbolAddress(&p, g_WcatT);  wcatT  = (float*)p;
    cudaGetSymbolAddress(&p, g_leafxW); leafxW = (float*)p;
    cudaGetSymbolAddress(&p, g_bzT);    bzT    = (float*)p;
    cudaGetSymbolAddress(&p, g_h676);   h676   = (float*)p;
    cudaGetSymbolAddress(&p, g_c676);   c676   = (float*)p;
    const float* wih = wcatT;
    const float* whh = wcatT + 256*1024;

    // prologue (persistent, 2 launches)
    k_preA<<<NB, 256>>>(Wt, Wc, bc, bt, W_ih, W_hh, b_ih, b_hh, emb, lstm_init);
    k_preB<<<NB, 256>>>(W_ih, b_ih, b_hh);

    const int leaf_off = 21845;   // (4^8-1)/3
    // level 7 (M=16384): t=2 gather-step, t=3 step, tag -> childA
    simt_gemm<4><<<dim3(256,8), 256>>>(h676, hA, c676, cbuf, whh,
                                       idents + leaf_off, leafxW, 0, 16384);
    simt_gemm<2><<<dim3(256,8), 256>>>(hA, hB, cbuf, cbuf, whh,
                                       idents + leaf_off + 3, leafxW, 0, 16384);
    tag_kernel<<<1024, 256>>>(hB, idents + 5461, chA, 16384);

    // levels 6..4
    struct Lvl { int M; float* chin; float* chout; int off; };
    Lvl lv[3] = {
        {4096, chA, chB, 1365},
        {1024, chB, chA, 341},
        {256,  chA, chB, 85},
    };
    for (int li = 0; li < 3; li++){
        int M = lv[li].M;
        int M4 = 4*M;
        simt_gemm<0><<<dim3(M4/64,8), 256>>>(lv[li].chin, xw, nullptr, nullptr, wih,
                                             nullptr, bzT, 0, M4);
        k_cell0<<<M, 256>>>(xw, hA, cbuf);
        for (int t = 1; t < 4; t++){
            const float* hin = (t & 1) ? hA : hB;
            float* hout = (t & 1) ? hB : hA;
            simt_gemm<1><<<dim3(M/64,8), 256>>>(hin, hout, cbuf, cbuf, whh,
                                                nullptr, xw, t, M);
        }
        tag_kernel<<<M/16, 256>>>(hB, idents + lv[li].off, lv[li].chout, M);
    }

    // tail: levels 3..0 (reads childB written by level-4 tag)
    k_tail<<<NB, 256>>>(idents, out);
}